// round 15
// baseline (speedup 1.0000x reference)
#include <cuda_runtime.h>
#include <cuda_bf16.h>
#include <math.h>
#include <stdint.h>

// Problem constants (fixed by setup_inputs)
#define BATCH    2
#define FRAMES   16
#define SPATIAL  1024          // 32*32
#define HIDDEN   1024
#define NHEADS   16
#define HDIM     64
#define SEQLEN   (FRAMES*SPATIAL)          // 16384
#define NTOK     (BATCH*SEQLEN)            // 32768
#define QKVDIM   (3*HIDDEN)                // 3072
#define KD       1024                      // K for both GEMMs

// ---------------------------------------------------------------------------
// Scratch (device globals: allocation-free, graph-capturable)
// ---------------------------------------------------------------------------
__device__ __align__(16) __nv_bfloat16 g_xn_hi [(size_t)NTOK * HIDDEN];
__device__ __align__(16) __nv_bfloat16 g_xn_lo [(size_t)NTOK * HIDDEN];
__device__ __align__(16) float         g_qkv   [(size_t)NTOK * QKVDIM];
__device__ __align__(16) __nv_bfloat16 g_att_hi[(size_t)NTOK * HIDDEN];
__device__ __align__(16) __nv_bfloat16 g_att_lo[(size_t)NTOK * HIDDEN];
__device__ __align__(16) __nv_bfloat16 g_wq_hi [(size_t)QKVDIM * HIDDEN];
__device__ __align__(16) __nv_bfloat16 g_wq_lo [(size_t)QKVDIM * HIDDEN];
__device__ __align__(16) __nv_bfloat16 g_wo_hi [(size_t)HIDDEN * HIDDEN];
__device__ __align__(16) __nv_bfloat16 g_wo_lo [(size_t)HIDDEN * HIDDEN];

// ---------------------------------------------------------------------------
// Helpers
// ---------------------------------------------------------------------------
__device__ __forceinline__ uint32_t smem_u32(const void* p) {
    uint32_t a;
    asm("{ .reg .u64 t; cvta.to.shared.u64 t, %1; cvt.u32.u64 %0, t; }" : "=r"(a) : "l"(p));
    return a;
}

__device__ __forceinline__ void cp_async16(uint32_t s, const void* g) {
    asm volatile("cp.async.cg.shared.global [%0], [%1], 16;" :: "r"(s), "l"(g));
}

__device__ __forceinline__ uint32_t pack_bf2(float a, float b) {
    __nv_bfloat162 t = __floats2bfloat162_rn(a, b);
    return *reinterpret_cast<uint32_t*>(&t);
}

#define LDM4(r, a) \
    asm volatile("ldmatrix.sync.aligned.m8n8.x4.shared.b16 {%0,%1,%2,%3}, [%4];" \
        : "=r"((r)[0]), "=r"((r)[1]), "=r"((r)[2]), "=r"((r)[3]) : "r"(a))

#define MMA16816(c, A, b0, b1) \
    asm volatile("mma.sync.aligned.m16n8k16.row.col.f32.bf16.bf16.f32 " \
        "{%0,%1,%2,%3}, {%4,%5,%6,%7}, {%8,%9}, {%0,%1,%2,%3};" \
        : "+f"((c)[0]), "+f"((c)[1]), "+f"((c)[2]), "+f"((c)[3]) \
        : "r"((A)[0]), "r"((A)[1]), "r"((A)[2]), "r"((A)[3]), "r"(b0), "r"(b1))

// ---------------------------------------------------------------------------
// Kernel 0: split weights into bf16 hi/lo
// ---------------------------------------------------------------------------
__global__ void __launch_bounds__(256) prep_w(
    const float4* __restrict__ wq, const float4* __restrict__ wo,
    uint2* __restrict__ qh, uint2* __restrict__ ql,
    uint2* __restrict__ oh, uint2* __restrict__ ol)
{
    const int i = blockIdx.x * 256 + threadIdx.x;     // 786432 float4s for w_qkv
    float4 w = wq[i];
    float hx = __bfloat162float(__float2bfloat16_rn(w.x));
    float hy = __bfloat162float(__float2bfloat16_rn(w.y));
    float hz = __bfloat162float(__float2bfloat16_rn(w.z));
    float hw = __bfloat162float(__float2bfloat16_rn(w.w));
    qh[i] = make_uint2(pack_bf2(w.x, w.y), pack_bf2(w.z, w.w));
    ql[i] = make_uint2(pack_bf2(w.x - hx, w.y - hy), pack_bf2(w.z - hz, w.w - hw));
    if (i < (HIDDEN * HIDDEN) / 4) {
        float4 v = wo[i];
        float vx = __bfloat162float(__float2bfloat16_rn(v.x));
        float vy = __bfloat162float(__float2bfloat16_rn(v.y));
        float vz = __bfloat162float(__float2bfloat16_rn(v.z));
        float vw = __bfloat162float(__float2bfloat16_rn(v.w));
        oh[i] = make_uint2(pack_bf2(v.x, v.y), pack_bf2(v.z, v.w));
        ol[i] = make_uint2(pack_bf2(v.x - vx, v.y - vy), pack_bf2(v.z - vz, v.w - vw));
    }
}

// ---------------------------------------------------------------------------
// Kernel 1: LayerNorm + temporal transpose, emitting bf16 hi/lo split
// ---------------------------------------------------------------------------
__inline__ __device__ float warpReduceSum(float v) {
#pragma unroll
    for (int o = 16; o > 0; o >>= 1) v += __shfl_down_sync(0xffffffffu, v, o);
    return v;
}

__global__ void __launch_bounds__(256) ln_kernel(
    const float* __restrict__ x,
    const float* __restrict__ gamma,
    const float* __restrict__ beta,
    __nv_bfloat16* __restrict__ xn_hi,
    __nv_bfloat16* __restrict__ xn_lo)
{
    const int token = blockIdx.x;
    const float4* row = (const float4*)(x + (size_t)token * HIDDEN);
    float4 v = row[threadIdx.x];
    float s  = v.x + v.y + v.z + v.w;
    float ss = v.x*v.x + v.y*v.y + v.z*v.z + v.w*v.w;

    __shared__ float sb[8], ssb[8];
    __shared__ float s_mean, s_inv;
    float ws  = warpReduceSum(s);
    float wss = warpReduceSum(ss);
    const int lane = threadIdx.x & 31, warp = threadIdx.x >> 5;
    if (lane == 0) { sb[warp] = ws; ssb[warp] = wss; }
    __syncthreads();
    if (threadIdx.x == 0) {
        float ts = 0.f, tss = 0.f;
#pragma unroll
        for (int i = 0; i < 8; i++) { ts += sb[i]; tss += ssb[i]; }
        float mean = ts * (1.0f / HIDDEN);
        float var  = tss * (1.0f / HIDDEN) - mean * mean;
        s_mean = mean;
        s_inv  = rsqrtf(var + 1e-5f);
    }
    __syncthreads();
    const float mean = s_mean, inv = s_inv;

    float4 g4 = ((const float4*)gamma)[threadIdx.x];
    float4 b4 = ((const float4*)beta )[threadIdx.x];
    float4 o;
    o.x = (v.x - mean) * inv * g4.x + b4.x;
    o.y = (v.y - mean) * inv * g4.y + b4.y;
    o.z = (v.z - mean) * inv * g4.z + b4.z;
    o.w = (v.w - mean) * inv * g4.w + b4.w;

    float hx = __bfloat162float(__float2bfloat16_rn(o.x));
    float hy = __bfloat162float(__float2bfloat16_rn(o.y));
    float hz = __bfloat162float(__float2bfloat16_rn(o.z));
    float hw = __bfloat162float(__float2bfloat16_rn(o.w));

    const int b  = token >> 14;
    const int rm = token & 16383;
    const int t  = rm >> 10;
    const int sp = rm & 1023;
    const int r  = b * 16384 + sp * 16 + t;
    ((uint2*)(xn_hi + (size_t)r * HIDDEN))[threadIdx.x] =
        make_uint2(pack_bf2(o.x, o.y), pack_bf2(o.z, o.w));
    ((uint2*)(xn_lo + (size_t)r * HIDDEN))[threadIdx.x] =
        make_uint2(pack_bf2(o.x - hx, o.y - hy), pack_bf2(o.z - hz, o.w - hw));
}

// ---------------------------------------------------------------------------
// Kernel 2/4: PERSISTENT bf16x3 error-compensated NT GEMM (mma.sync HMMA).
//   C[M,N] = (Ah+Al)[M,K] * (Bh+Bl)[N,K]^T ~= Ah*Bh + Al*Bh + Ah*Bl
//   152 persistent CTAs; each CTA processes tiles bid, bid+grid, ... with
//   ALL k-stages forming one flat 3-deep cp.async stream, so the next tile's
//   loads overlap the current tile's tail MMAs and epilogue.
//   Per-tile config identical to R14 (known good): 128x128, BK=64, SW128
//   swizzle, 256 thr = 8 warps (4m x 2n), warp tile 32x64, fp32 accum.
// ---------------------------------------------------------------------------
#define BK      64
#define STG     3
#define TILE_B  16384                      // one 128x64 bf16 tile
#define STAGE_B (4 * TILE_B)               // Ah | Al | Bh | Bl
#define SMEM_GEMM (STG * STAGE_B)          // 196608
#define NITER   (KD / BK)                  // 16 k-stages per tile
#define GRID_P  152

__global__ void __launch_bounds__(256) gemm_bf16x3(
    const __nv_bfloat16* __restrict__ Ah, const __nv_bfloat16* __restrict__ Al,
    const __nv_bfloat16* __restrict__ Bh, const __nv_bfloat16* __restrict__ Bl,
    float* __restrict__ C, int N, int gx, int ntiles)
{
    extern __shared__ char smem[];
    const uint32_t sb = smem_u32(smem);

    const int tid  = threadIdx.x;
    const int lane = tid & 31;
    const int w    = tid >> 5;
    const int wm   = w & 3;          // 4 m-warps (32 rows each)
    const int wn   = w >> 2;         // 2 n-warps (64 cols each)
    const int bid  = blockIdx.x;
    const int grid = gridDim.x;

    const int nt_own = (ntiles - bid + grid - 1) / grid;   // tiles for this CTA
    const int own    = nt_own * NITER;                     // flat stage count

    // ldmatrix lane-address precompute (SW128: chunk' = chunk ^ (row & 7))
    const int csel = lane >> 4;
    uint32_t aBase[2]; int swA[2];
#pragma unroll
    for (int mt = 0; mt < 2; mt++) {
        int row = wm * 32 + mt * 16 + (lane & 15);
        aBase[mt] = (uint32_t)row * 128; swA[mt] = row & 7;
    }
    uint32_t bBase[4]; int swB[4];
#pragma unroll
    for (int pt = 0; pt < 4; pt++) {
        int row = wn * 64 + pt * 16 + (lane & 15);
        bBase[pt] = (uint32_t)row * 128; swB[pt] = row & 7;
    }

    // ---- load-side tile state ----
    int ld_t = bid, ld_kk = 0;
    const __nv_bfloat16 *pAh, *pAl, *pBh, *pBl;
    auto set_ld = [&](int t) {
        const int by = t / gx, bx = t % gx;
        pAh = Ah + (size_t)by * 128 * KD;
        pAl = Al + (size_t)by * 128 * KD;
        pBh = Bh + (size_t)bx * 128 * KD;
        pBl = Bl + (size_t)bx * 128 * KD;
    };
    set_ld(ld_t);

    auto load_stage = [&](int s) {
        const uint32_t st = sb + (uint32_t)(s % STG) * STAGE_B;
        const int k0 = ld_kk * BK;
#pragma unroll
        for (int i = 0; i < 4; i++) {
            const int cidx = tid + i * 256;          // 0..1023
            const int r = cidx >> 3, ch = cidx & 7;
            const uint32_t so = (uint32_t)r * 128 + ((ch ^ (r & 7)) << 4);
            const size_t go = (size_t)r * KD + k0 + ch * 8;
            cp_async16(st + 0*TILE_B + so, pAh + go);
            cp_async16(st + 1*TILE_B + so, pAl + go);
            cp_async16(st + 2*TILE_B + so, pBh + go);
            cp_async16(st + 3*TILE_B + so, pBl + go);
        }
        if (++ld_kk == NITER) {
            ld_kk = 0;
            ld_t += grid;
            if (ld_t < ntiles) set_ld(ld_t);
        }
    };

    // ---- compute-side tile state ----
    int cp_t = bid, cp_kk = 0;
    int cby = cp_t / gx, cbx = cp_t % gx;

    float acc[2][8][4];

    // prologue: stages 0,1
    load_stage(0);
    asm volatile("cp.async.commit_group;" ::: "memory");
    load_stage(1);
    asm volatile("cp.async.commit_group;" ::: "memory");

    for (int s = 0; s < own; ++s) {
        asm volatile("cp.async.wait_group %0;" :: "n"(1));   // stage s complete
        __syncthreads();                                     // all warps done with stage s-1

        if (s + 2 < own) load_stage(s + 2);                  // buf (s-1)%3: safe after sync
        asm volatile("cp.async.commit_group;" ::: "memory");

        if (cp_kk == 0) {
#pragma unroll
            for (int i = 0; i < 2; i++)
#pragma unroll
                for (int j = 0; j < 8; j++)
#pragma unroll
                    for (int q = 0; q < 4; q++) acc[i][j][q] = 0.f;
        }

        const uint32_t st = sb + (uint32_t)(s % STG) * STAGE_B;
#pragma unroll
        for (int ks = 0; ks < 4; ks++) {
            const int kc = ks * 2;
            uint32_t ah[2][4], al[2][4];
#pragma unroll
            for (int mt = 0; mt < 2; mt++) {
                const uint32_t ad = st + aBase[mt] + (((kc + csel) ^ swA[mt]) << 4);
                LDM4(ah[mt], ad);
                LDM4(al[mt], ad + TILE_B);
            }
            uint32_t bh[4][4], bl[4][4];
#pragma unroll
            for (int pt = 0; pt < 4; pt++) {
                const uint32_t bd = st + 2*TILE_B + bBase[pt] + (((kc + csel) ^ swB[pt]) << 4);
                LDM4(bh[pt], bd);
                LDM4(bl[pt], bd + TILE_B);
            }
#pragma unroll
            for (int mt = 0; mt < 2; mt++)
#pragma unroll
                for (int nt = 0; nt < 8; nt++) {
                    const int pt = nt >> 1, hf = nt & 1;
                    MMA16816(acc[mt][nt], ah[mt], bh[pt][hf], bh[pt][2 + hf]);
                    MMA16816(acc[mt][nt], al[mt], bh[pt][hf], bh[pt][2 + hf]);
                    MMA16816(acc[mt][nt], ah[mt], bl[pt][hf], bl[pt][2 + hf]);
                }
        }

        if (++cp_kk == NITER) {
            // epilogue for tile (cby, cbx): register->gmem only, no smem, no sync
#pragma unroll
            for (int mt = 0; mt < 2; mt++) {
                const int row = cby * 128 + wm * 32 + mt * 16 + (lane >> 2);
#pragma unroll
                for (int nt = 0; nt < 8; nt++) {
                    const int col = cbx * 128 + wn * 64 + nt * 8 + 2 * (lane & 3);
                    float* p = C + (size_t)row * N + col;
                    *(float2*)p                   = make_float2(acc[mt][nt][0], acc[mt][nt][1]);
                    *(float2*)(p + 8 * (size_t)N) = make_float2(acc[mt][nt][2], acc[mt][nt][3]);
                }
            }
            cp_kk = 0;
            cp_t += grid;
            if (cp_t < ntiles) { cby = cp_t / gx; cbx = cp_t % gx; }
        }
    }
}

// ---------------------------------------------------------------------------
// Kernel 3: per-(n,h) RoPE + causal attention.
//   RoPE computed in registers via shfl_xor(.,8) partner exchange (d <-> d+-32
//   is lane^8 within the same warp) — no raw q/k smem staging, one fewer sync,
//   smem 22KB -> ~13KB (occupancy 61% -> ~100%).
// ---------------------------------------------------------------------------
__device__ __forceinline__ float4 shfl_xor4(float4 a, int m) {
    a.x = __shfl_xor_sync(0xffffffffu, a.x, m);
    a.y = __shfl_xor_sync(0xffffffffu, a.y, m);
    a.z = __shfl_xor_sync(0xffffffffu, a.z, m);
    a.w = __shfl_xor_sync(0xffffffffu, a.w, m);
    return a;
}

__global__ void __launch_bounds__(128) attn_kernel(
    const float* __restrict__ qkv,
    __nv_bfloat16* __restrict__ att_hi,
    __nv_bfloat16* __restrict__ att_lo)
{
    __shared__ float qr[16*64], kr[16*64], vs[16*64];
    __shared__ float p[16][17];

    const int nh = blockIdx.x;
    const int n  = nh >> 4;
    const int hh = nh & 15;
    const int tid = threadIdx.x;

    const float* base = qkv + (size_t)n * FRAMES * QKVDIM + hh * HDIM;

    // Each thread owns float4 elements i = tid and i = tid+128 (t = i>>4, f = i&15).
    float4 q[2], k[2], v[2];
#pragma unroll
    for (int j = 0; j < 2; j++) {
        const int i = tid + j * 128;
        const int t = i >> 4, f = i & 15;
        const float4* rp = (const float4*)(base + (size_t)t * QKVDIM);
        q[j] = rp[f];
        k[j] = rp[256 + f];
        v[j] = rp[512 + f];
    }

    // Partner (f^8 i.e. d+-32) lives at lane^8 in the same warp for both j.
    float4 qp[2], kp[2];
#pragma unroll
    for (int j = 0; j < 2; j++) {
        qp[j] = shfl_xor4(q[j], 8);
        kp[j] = shfl_xor4(k[j], 8);
    }

    // RoPE factors: d = 4f+e, d&31 = 4*(f&7)+e (same f for both j).
    {
        const int f  = tid & 15;
        const int fm = f & 7;
        const float sgn = (f < 8) ? -1.0f : 1.0f;
        float invf[4];
#pragma unroll
        for (int e = 0; e < 4; e++)
            invf[e] = expf(-(float)(4 * fm + e) * (9.210340371976184f / 32.0f));
#pragma unroll
        for (int j = 0; j < 2; j++) {
            const int i = tid + j * 128;
            const float t = (float)(i >> 4);
            float sn, cs;
            float4 qo, ko;
            sincosf(t * invf[0], &sn, &cs);
            qo.x = q[j].x * cs + sgn * qp[j].x * sn;
            ko.x = k[j].x * cs + sgn * kp[j].x * sn;
            sincosf(t * invf[1], &sn, &cs);
            qo.y = q[j].y * cs + sgn * qp[j].y * sn;
            ko.y = k[j].y * cs + sgn * kp[j].y * sn;
            sincosf(t * invf[2], &sn, &cs);
            qo.z = q[j].z * cs + sgn * qp[j].z * sn;
            ko.z = k[j].z * cs + sgn * kp[j].z * sn;
            sincosf(t * invf[3], &sn, &cs);
            qo.w = q[j].w * cs + sgn * qp[j].w * sn;
            ko.w = k[j].w * cs + sgn * kp[j].w * sn;
            ((float4*)qr)[i] = qo;
            ((float4*)kr)[i] = ko;
            ((float4*)vs)[i] = v[j];
        }
    }
    __syncthreads();

    // scores (causal), scale = 0.125
#pragma unroll
    for (int e = tid; e < 256; e += 128) {
        const int qi = e >> 4, kj = e & 15;
        float sc;
        if (kj > qi) sc = -INFINITY;
        else {
            float dsum = 0.f;
#pragma unroll
            for (int d = 0; d < 64; d++) dsum = fmaf(qr[qi*64+d], kr[kj*64+d], dsum);
            sc = dsum * 0.125f;
        }
        p[qi][kj] = sc;
    }
    __syncthreads();

    if (tid < 16) {
        float mx = -INFINITY;
#pragma unroll
        for (int j = 0; j < 16; j++) mx = fmaxf(mx, p[tid][j]);
        float sum = 0.f;
#pragma unroll
        for (int j = 0; j < 16; j++) {
            float e2 = (j <= tid) ? expf(p[tid][j] - mx) : 0.f;
            p[tid][j] = e2;
            sum += e2;
        }
        const float isum = 1.0f / sum;
#pragma unroll
        for (int j = 0; j < 16; j++) p[tid][j] *= isum;
    }
    __syncthreads();

    // out = attn @ v; packed bf16x2 stores of hi and lo
    const int b = n >> 10, sp = n & 1023;
#pragma unroll
    for (int i = tid; i < 512; i += 128) {
        const int t = i >> 5, dp = i & 31;     // element pair d = 2*dp
        float o0 = 0.f, o1 = 0.f;
#pragma unroll
        for (int kk = 0; kk < 16; kk++) {
            const float wgt = p[t][kk];
            o0 = fmaf(wgt, vs[kk*64 + 2*dp],     o0);
            o1 = fmaf(wgt, vs[kk*64 + 2*dp + 1], o1);
        }
        const size_t idx = (size_t)(b * SEQLEN + t * SPATIAL + sp) * HIDDEN + hh * HDIM + 2 * dp;
        const float h0 = __bfloat162float(__float2bfloat16_rn(o0));
        const float h1 = __bfloat162float(__float2bfloat16_rn(o1));
        *(uint32_t*)(att_hi + idx) = pack_bf2(o0, o1);
        *(uint32_t*)(att_lo + idx) = pack_bf2(o0 - h0, o1 - h1);
    }
}

// ---------------------------------------------------------------------------
extern "C" void kernel_launch(void* const* d_in, const int* in_sizes, int n_in,
                              void* d_out, int out_size)
{
    const float* x      = (const float*)d_in[0];
    const float* w_qkv  = (const float*)d_in[1];
    const float* w_out  = (const float*)d_in[2];
    const float* gamma  = (const float*)d_in[3];
    const float* beta   = (const float*)d_in[4];
    float* out = (float*)d_out;

    __nv_bfloat16 *xnh, *xnl, *ath, *atl, *wqh, *wql, *woh, *wol;
    float *qkv;
    cudaGetSymbolAddress((void**)&xnh, g_xn_hi);
    cudaGetSymbolAddress((void**)&xnl, g_xn_lo);
    cudaGetSymbolAddress((void**)&qkv, g_qkv);
    cudaGetSymbolAddress((void**)&ath, g_att_hi);
    cudaGetSymbolAddress((void**)&atl, g_att_lo);
    cudaGetSymbolAddress((void**)&wqh, g_wq_hi);
    cudaGetSymbolAddress((void**)&wql, g_wq_lo);
    cudaGetSymbolAddress((void**)&woh, g_wo_hi);
    cudaGetSymbolAddress((void**)&wol, g_wo_lo);

    cudaFuncSetAttribute(gemm_bf16x3, cudaFuncAttributeMaxDynamicSharedMemorySize, SMEM_GEMM);

    // 0) Split weights into bf16 hi/lo
    prep_w<<<(QKVDIM * HIDDEN / 4) / 256, 256>>>(
        (const float4*)w_qkv, (const float4*)w_out,
        (uint2*)wqh, (uint2*)wql, (uint2*)woh, (uint2*)wol);

    // 1) LayerNorm + temporal transpose (bf16 split output)
    ln_kernel<<<NTOK, 256>>>(x, gamma, beta, xnh, xnl);

    // 2) QKV GEMM: [32768,1024] x [3072,1024]^T -> [32768,3072] fp32
    gemm_bf16x3<<<GRID_P, 256, SMEM_GEMM>>>(
        xnh, xnl, wqh, wql, qkv, QKVDIM, QKVDIM / 128, (QKVDIM / 128) * (NTOK / 128));

    // 3) RoPE + causal attention per (n, h), bf16 split output
    attn_kernel<<<BATCH * SPATIAL * NHEADS, 128>>>(qkv, ath, atl);

    // 4) Output projection: [32768,1024] x [1024,1024]^T -> d_out fp32
    gemm_bf16x3<<<GRID_P, 256, SMEM_GEMM>>>(
        ath, atl, woh, wol, out, HIDDEN, HIDDEN / 128, (HIDDEN / 128) * (NTOK / 128));
}